// round 9
// baseline (speedup 1.0000x reference)
#include <cuda_runtime.h>
#include <cuda_fp16.h>

#define THREADS 512
#define RPW 8            // rows per warp
#define TROWS 128        // tile rows (16 warps x 8 rows)

typedef unsigned long long ull;

// ---------------- f32x2 helpers (sm_103a packed fp32 FFMA2) ----------------
__device__ __forceinline__ ull pack2(float lo, float hi) {
    ull r;
    asm("mov.b64 %0, {%1, %2};" : "=l"(r) : "r"(__float_as_uint(lo)), "r"(__float_as_uint(hi)));
    return r;
}
__device__ __forceinline__ void fma2(ull &acc, ull a, ull b) {
    asm("fma.rn.f32x2 %0, %1, %2, %0;" : "+l"(acc) : "l"(a), "l"(b));
}
__device__ __forceinline__ float2 unpack2(ull v) {
    unsigned int lo, hi;
    asm("mov.b64 {%0, %1}, %2;" : "=r"(lo), "=r"(hi) : "l"(v));
    return make_float2(__uint_as_float(lo), __uint_as_float(hi));
}

// Lloyd-Max bucketize (matches jnp.searchsorted side='left' over interior boundaries)
__device__ __forceinline__ float quantize1(float v, const float* __restrict__ sB,
                                           const float* __restrict__ sC) {
    int idx = (v > sB[8]) ? 8 : 0;
    idx += (v > sB[idx + 4]) ? 4 : 0;
    idx += (v > sB[idx + 2]) ? 2 : 0;
    idx += (v > sB[idx + 1]) ? 1 : 0;
    return sC[idx];
}

__global__ __launch_bounds__(THREADS, 1)
void tq_kernel(const float* __restrict__ x, const float* __restrict__ Pi,
               const float* __restrict__ cen, const float* __restrict__ bnd,
               float* __restrict__ out, int n_tiles)
{
    extern __shared__ char smem_raw[];
    ull*   PiKP = reinterpret_cast<ull*>(smem_raw);        // [64][128]: (Pi[j][2kp], Pi[j][2kp+1])
    ull*   PiJP = PiKP + 64 * 128;                         // [64][128]: (Pi[2jp][k], Pi[2jp+1][k])
    float* sX   = reinterpret_cast<float*>(PiJP + 64 * 128); // [128][128] x tile / values tile
    float* sRn  = sX  + 128 * 128;                         // [128]
    float* sNq  = sRn + 128;                               // [128]
    float* sB   = sNq + 128;                               // [16]
    float* sC   = sB  + 16;                                // [16]

    const int tid  = threadIdx.x;
    const int w    = tid >> 5;           // warp 0..15 owns rows w*8..w*8+7
    const int lane = tid & 31;
    const int r0   = w * RPW;

    // ---- build PiKP / PiJP once per block ----
    #pragma unroll
    for (int it = 0; it < 16; ++it) {
        int idx = it * THREADS + tid;    // 8192 entries
        int kp = idx >> 7, j = idx & 127;
        float2 v = *reinterpret_cast<const float2*>(Pi + j * 128 + 2 * kp);
        PiKP[kp * 128 + j] = pack2(v.x, v.y);
    }
    #pragma unroll
    for (int it = 0; it < 16; ++it) {
        int idx = it * THREADS + tid;
        int jp = idx >> 7, k = idx & 127;
        PiJP[jp * 128 + k] = pack2(Pi[(2 * jp) * 128 + k], Pi[(2 * jp + 1) * 128 + k]);
    }
    if (tid < 16) sC[tid] = cen[tid];
    if (tid < 16) sB[tid] = bnd[tid];
    __syncthreads();

    for (int tile = blockIdx.x; tile < n_tiles; tile += gridDim.x) {
        const float* gx   = x   + (size_t)tile * TROWS * 128;
        float*       gout = out + (size_t)tile * TROWS * 128;

        // ---- stage own 8 rows + norms (warp-exclusive; no block sync anywhere in loop) ----
        #pragma unroll
        for (int i = 0; i < RPW; ++i) {
            int r = r0 + i;
            float4 v = *reinterpret_cast<const float4*>(gx + r * 128 + lane * 4);
            *reinterpret_cast<float4*>(sX + r * 128 + lane * 4) = v;
            float s = v.x * v.x + v.y * v.y + v.z * v.z + v.w * v.w;
            s += __shfl_xor_sync(0xffffffffu, s, 16);
            s += __shfl_xor_sync(0xffffffffu, s, 8);
            s += __shfl_xor_sync(0xffffffffu, s, 4);
            s += __shfl_xor_sync(0xffffffffu, s, 2);
            s += __shfl_xor_sync(0xffffffffu, s, 1);
            if (lane == 0) {
                float nrm = sqrtf(s);
                sRn[r] = 1.0f / (nrm + 1e-8f);
                sNq[r] = __half2float(__float2half_rn(nrm));
            }
        }
        __syncwarp();

        // ---- GEMM 1: rot[r][j] = sum_k x[r][k]*Pi[j][k], f32x2 paired along k ----
        // thread cols: j = lane + 32*jj (jj<4); acc lo=even k, hi=odd k
        ull acc[RPW][4];
        #pragma unroll
        for (int i = 0; i < RPW; ++i)
            #pragma unroll
            for (int jj = 0; jj < 4; ++jj) acc[i][jj] = 0ull;

        #pragma unroll 4
        for (int kb = 0; kb < 32; ++kb) {
            const ull* p0 = PiKP + (2 * kb) * 128 + lane;     // kp = 2kb
            const ull* p1 = p0 + 128;                         // kp = 2kb+1
            ull b00 = p0[0], b01 = p0[32], b02 = p0[64], b03 = p0[96];
            ull b10 = p1[0], b11 = p1[32], b12 = p1[64], b13 = p1[96];
            #pragma unroll
            for (int i = 0; i < RPW; ++i) {
                ulonglong2 au = *reinterpret_cast<const ulonglong2*>(sX + (r0 + i) * 128 + kb * 4);
                fma2(acc[i][0], au.x, b00);
                fma2(acc[i][1], au.x, b01);
                fma2(acc[i][2], au.x, b02);
                fma2(acc[i][3], au.x, b03);
                fma2(acc[i][0], au.y, b10);
                fma2(acc[i][1], au.y, b11);
                fma2(acc[i][2], au.y, b12);
                fma2(acc[i][3], au.y, b13);
            }
        }
        __syncwarp();  // all lanes done reading x rows before overwriting with values

        // ---- quantize -> values tile (own rows) ----
        #pragma unroll
        for (int i = 0; i < RPW; ++i) {
            int r = r0 + i;
            float rn = sRn[r];
            #pragma unroll
            for (int jj = 0; jj < 4; ++jj) {
                float2 p = unpack2(acc[i][jj]);
                float v = (p.x + p.y) * rn;
                sX[r * 128 + lane + 32 * jj] = quantize1(v, sB, sC);
            }
        }
        __syncwarp();

        // ---- GEMM 2: recon[r][k] = sum_j values[r][j]*Pi[j][k], paired along j ----
        ull acc2[RPW][4];
        #pragma unroll
        for (int i = 0; i < RPW; ++i)
            #pragma unroll
            for (int jj = 0; jj < 4; ++jj) acc2[i][jj] = 0ull;

        #pragma unroll 4
        for (int jb = 0; jb < 32; ++jb) {
            const ull* q0 = PiJP + (2 * jb) * 128 + lane;     // jp = 2jb
            const ull* q1 = q0 + 128;                         // jp = 2jb+1
            ull b00 = q0[0], b01 = q0[32], b02 = q0[64], b03 = q0[96];
            ull b10 = q1[0], b11 = q1[32], b12 = q1[64], b13 = q1[96];
            #pragma unroll
            for (int i = 0; i < RPW; ++i) {
                ulonglong2 au = *reinterpret_cast<const ulonglong2*>(sX + (r0 + i) * 128 + jb * 4);
                fma2(acc2[i][0], au.x, b00);
                fma2(acc2[i][1], au.x, b01);
                fma2(acc2[i][2], au.x, b02);
                fma2(acc2[i][3], au.x, b03);
                fma2(acc2[i][0], au.y, b10);
                fma2(acc2[i][1], au.y, b11);
                fma2(acc2[i][2], au.y, b12);
                fma2(acc2[i][3], au.y, b13);
            }
        }
        __syncwarp();  // values reads done before next tile's staging overwrites

        // ---- scale by fp16-roundtripped norm, store ----
        #pragma unroll
        for (int i = 0; i < RPW; ++i) {
            int r = r0 + i;
            float nq = sNq[r];
            #pragma unroll
            for (int jj = 0; jj < 4; ++jj) {
                float2 p = unpack2(acc2[i][jj]);
                gout[r * 128 + lane + 32 * jj] = (p.x + p.y) * nq;
            }
        }
    }
}

extern "C" void kernel_launch(void* const* d_in, const int* in_sizes, int n_in,
                              void* d_out, int out_size) {
    const float* x   = (const float*)d_in[0];
    const float* Pi  = (const float*)d_in[1];
    const float* cen = (const float*)d_in[2];
    const float* bnd = (const float*)d_in[3];
    float* out = (float*)d_out;

    int N = in_sizes[0] / 128;
    int n_tiles = N / TROWS;

    int nsm = 148;
    cudaDeviceGetAttribute(&nsm, cudaDevAttrMultiProcessorCount, 0);
    if (nsm <= 0) nsm = 148;

    size_t smem_bytes = 2 * 64 * 128 * sizeof(ull)      // PiKP + PiJP
                      + 128 * 128 * sizeof(float)       // sX
                      + (128 + 128 + 16 + 16) * sizeof(float);
    cudaFuncSetAttribute(tq_kernel, cudaFuncAttributeMaxDynamicSharedMemorySize, (int)smem_bytes);

    tq_kernel<<<nsm, THREADS, smem_bytes>>>(x, Pi, cen, bnd, out, n_tiles);
}